// round 3
// baseline (speedup 1.0000x reference)
#include <cuda_runtime.h>
#include <math.h>

#define NB   4
#define NH   8
#define SEQ  2048
#define DIM  512
#define DH   64
#define MROWS (NB*SEQ)   // 8192

// ---- scratch (static device globals; no allocation at runtime) ----
__device__ float g_Q [MROWS*DIM];
__device__ float g_K [MROWS*DIM];
__device__ float g_V [MROWS*DIM];
__device__ float g_XK[MROWS*DIM];
__device__ float g_XV[MROWS*DIM];
__device__ float g_AO[MROWS*DIM];

// ============================================================
// GEMM: C[M,N] = A[M,512] * B[512,N] (+ bias), M=8192, N=512
// Tiles: 128x64x16, 256 threads, 8x4 per-thread micro-tile.
// ============================================================
#define GBM 128
#define GBN 64
#define GBK 16

__global__ __launch_bounds__(256) void gemm_kernel(
    const float* __restrict__ A, const float* __restrict__ Bm,
    const float* __restrict__ bias, float* __restrict__ C)
{
    __shared__ float As[GBK][GBM];   // transposed A tile
    __shared__ float Bs[GBK][GBN];

    const int tid = threadIdx.x;
    const int tx  = tid & 15;        // N direction (x4)
    const int ty  = tid >> 4;        // M direction (x8)
    const int bm  = blockIdx.y * GBM;
    const int bn  = blockIdx.x * GBN;

    // A loader: 2 float4 per thread
    const int arow0 = tid >> 2;          // 0..63
    const int acg   = (tid & 3) * 4;     // 0,4,8,12
    const int arow1 = arow0 + 64;
    // B loader: 1 float4 per thread
    const int brow  = tid >> 4;          // 0..15
    const int bc    = (tid & 15) * 4;    // 0..60

    float acc[8][4];
    #pragma unroll
    for (int i = 0; i < 8; i++)
        #pragma unroll
        for (int j = 0; j < 4; j++) acc[i][j] = 0.f;

    for (int k0 = 0; k0 < DIM; k0 += GBK) {
        float4 a0 = *(const float4*)(A  + (size_t)(bm + arow0) * DIM + k0 + acg);
        float4 a1 = *(const float4*)(A  + (size_t)(bm + arow1) * DIM + k0 + acg);
        float4 b0 = *(const float4*)(Bm + (size_t)(k0 + brow) * DIM + bn + bc);
        __syncthreads();   // previous-iteration compute done
        As[acg+0][arow0] = a0.x; As[acg+1][arow0] = a0.y;
        As[acg+2][arow0] = a0.z; As[acg+3][arow0] = a0.w;
        As[acg+0][arow1] = a1.x; As[acg+1][arow1] = a1.y;
        As[acg+2][arow1] = a1.z; As[acg+3][arow1] = a1.w;
        *(float4*)&Bs[brow][bc] = b0;
        __syncthreads();

        #pragma unroll
        for (int k = 0; k < GBK; k++) {
            float4 av0 = *(const float4*)&As[k][ty*8];
            float4 av1 = *(const float4*)&As[k][ty*8+4];
            float4 bv  = *(const float4*)&Bs[k][tx*4];
            float a[8] = {av0.x,av0.y,av0.z,av0.w,av1.x,av1.y,av1.z,av1.w};
            float b[4] = {bv.x,bv.y,bv.z,bv.w};
            #pragma unroll
            for (int i = 0; i < 8; i++)
                #pragma unroll
                for (int j = 0; j < 4; j++)
                    acc[i][j] = fmaf(a[i], b[j], acc[i][j]);
        }
    }

    float4 bb = make_float4(0.f, 0.f, 0.f, 0.f);
    if (bias) bb = *(const float4*)(bias + bn + tx*4);
    #pragma unroll
    for (int i = 0; i < 8; i++) {
        const int row = bm + ty*8 + i;
        float4 out;
        out.x = acc[i][0] + bb.x;
        out.y = acc[i][1] + bb.y;
        out.z = acc[i][2] + bb.z;
        out.w = acc[i][3] + bb.w;
        *(float4*)(C + (size_t)row * DIM + bn + tx*4) = out;
    }
}

// ============================================================
// Flash attention with diagonal term.
// Grid: (SEQ/64 q-tiles, NB*NH). 256 threads.
//  thread (ty=tid/16, tx=tid%16) owns q-rows ty*4..+3 and
//  kv-cols / dh-cols tx*4..+3 (4x4 fragments).
// ============================================================
#define PADQ 68   // float4-aligned padded row for Qt/KV tiles
#define PADP 69   // odd-ish pad for transposed P (2-way store conflicts)

__global__ __launch_bounds__(256) void attn_kernel(
    const float* __restrict__ Q,  const float* __restrict__ K,
    const float* __restrict__ V,  const float* __restrict__ XK,
    const float* __restrict__ XV, float* __restrict__ O)
{
    extern __shared__ float sm[];
    float* Qt = sm;                  // [64][PADQ] : Qt[d][q]
    float* KV = sm + 64*PADQ;        // [64][PADQ] : Kt[d][kv] then V[kv][dh]
    float* Pt = sm + 2*64*PADQ;      // [64][PADP] : Pt[kv][q]

    const int tid = threadIdx.x;
    const int tx  = tid & 15;
    const int ty  = tid >> 4;
    const int bh  = blockIdx.y;
    const int b   = bh >> 3;
    const int h   = bh & 7;
    const int q0  = blockIdx.x * 64;
    const float scale = 0.125f;      // 1/sqrt(64)

    const float* Qb = Q + ((size_t)b*SEQ)*DIM + h*DH;
    const float* Kb = K + ((size_t)b*SEQ)*DIM + h*DH;
    const float* Vb = V + ((size_t)b*SEQ)*DIM + h*DH;

    const int lr = tid >> 4;         // loader row base 0..15
    const int lc = (tid & 15) * 4;   // loader col 0..60

    // load Q tile transposed: Qt[d][q]
    #pragma unroll
    for (int it = 0; it < 4; it++) {
        const int r = lr + it*16;
        float4 v = *(const float4*)(Qb + (size_t)(q0 + r)*DIM + lc);
        Qt[(lc+0)*PADQ + r] = v.x;
        Qt[(lc+1)*PADQ + r] = v.y;
        Qt[(lc+2)*PADQ + r] = v.z;
        Qt[(lc+3)*PADQ + r] = v.w;
    }

    float m[4], l[4], o[4][4];
    #pragma unroll
    for (int i = 0; i < 4; i++) {
        m[i] = -1e30f; l[i] = 0.f;
        #pragma unroll
        for (int j = 0; j < 4; j++) o[i][j] = 0.f;
    }

    for (int t = 0; t < SEQ/64; t++) {
        __syncthreads();  // previous PV GEMM done reading KV/Pt
        // load K tile transposed: Kt[d][kv]
        #pragma unroll
        for (int it = 0; it < 4; it++) {
            const int r = lr + it*16;
            float4 v = *(const float4*)(Kb + (size_t)(t*64 + r)*DIM + lc);
            KV[(lc+0)*PADQ + r] = v.x;
            KV[(lc+1)*PADQ + r] = v.y;
            KV[(lc+2)*PADQ + r] = v.z;
            KV[(lc+3)*PADQ + r] = v.w;
        }
        __syncthreads();

        // S = Q K^T  (outer product over d)
        float s[4][4];
        #pragma unroll
        for (int i = 0; i < 4; i++)
            #pragma unroll
            for (int j = 0; j < 4; j++) s[i][j] = 0.f;
        #pragma unroll 8
        for (int d = 0; d < 64; d++) {
            float4 qa = *(const float4*)&Qt[d*PADQ + ty*4];
            float4 ka = *(const float4*)&KV[d*PADQ + tx*4];
            float qr[4] = {qa.x,qa.y,qa.z,qa.w};
            float kr[4] = {ka.x,ka.y,ka.z,ka.w};
            #pragma unroll
            for (int i = 0; i < 4; i++)
                #pragma unroll
                for (int j = 0; j < 4; j++)
                    s[i][j] = fmaf(qr[i], kr[j], s[i][j]);
        }

        // online softmax per q-row; P written transposed to Pt[kv][q]
        #pragma unroll
        for (int i = 0; i < 4; i++) {
            #pragma unroll
            for (int j = 0; j < 4; j++) s[i][j] *= scale;
            float rm = fmaxf(fmaxf(s[i][0], s[i][1]), fmaxf(s[i][2], s[i][3]));
            #pragma unroll
            for (int msk = 8; msk >= 1; msk >>= 1)
                rm = fmaxf(rm, __shfl_xor_sync(0xffffffffu, rm, msk));
            const float mn   = fmaxf(m[i], rm);
            const float corr = __expf(m[i] - mn);
            float p[4], ps = 0.f;
            #pragma unroll
            for (int j = 0; j < 4; j++) { p[j] = __expf(s[i][j] - mn); ps += p[j]; }
            #pragma unroll
            for (int msk = 8; msk >= 1; msk >>= 1)
                ps += __shfl_xor_sync(0xffffffffu, ps, msk);
            l[i] = l[i]*corr + ps;
            m[i] = mn;
            #pragma unroll
            for (int j = 0; j < 4; j++) o[i][j] *= corr;
            #pragma unroll
            for (int j = 0; j < 4; j++)
                Pt[(tx*4+j)*PADP + ty*4 + i] = p[j];
        }
        __syncthreads();  // Pt complete, S-phase reads of KV(K) done

        // load V tile natural: V[kv][dh]
        #pragma unroll
        for (int it = 0; it < 4; it++) {
            const int r = lr + it*16;
            float4 v = *(const float4*)(Vb + (size_t)(t*64 + r)*DIM + lc);
            *(float4*)&KV[r*PADQ + lc] = v;
        }
        __syncthreads();

        // O += P V  (outer product over kv)
        #pragma unroll 8
        for (int kv = 0; kv < 64; kv++) {
            float a0 = Pt[kv*PADP + ty*4 + 0];
            float a1 = Pt[kv*PADP + ty*4 + 1];
            float a2 = Pt[kv*PADP + ty*4 + 2];
            float a3 = Pt[kv*PADP + ty*4 + 3];
            float4 bv = *(const float4*)&KV[kv*PADQ + tx*4];
            float br[4] = {bv.x,bv.y,bv.z,bv.w};
            float ar[4] = {a0,a1,a2,a3};
            #pragma unroll
            for (int i = 0; i < 4; i++)
                #pragma unroll
                for (int j = 0; j < 4; j++)
                    o[i][j] = fmaf(ar[i], br[j], o[i][j]);
        }
    }

    // ---- diagonal term: logit = scale * dot(q, xq_k); value = xq_v ----
    __syncthreads();
    const float* XKb = XK + ((size_t)b*SEQ)*DIM + h*DH;
    #pragma unroll
    for (int it = 0; it < 4; it++) {
        const int r = lr + it*16;
        float4 v = *(const float4*)(XKb + (size_t)(q0 + r)*DIM + lc);
        KV[(lc+0)*PADQ + r] = v.x;
        KV[(lc+1)*PADQ + r] = v.y;
        KV[(lc+2)*PADQ + r] = v.z;
        KV[(lc+3)*PADQ + r] = v.w;
    }
    __syncthreads();

    const float* XVb = XV + ((size_t)b*SEQ)*DIM + h*DH;
    float*       Ob  = O  + ((size_t)b*SEQ)*DIM + h*DH;
    #pragma unroll
    for (int i = 0; i < 4; i++) {
        const int row = ty*4 + i;
        float dl = 0.f;
        #pragma unroll
        for (int u = 0; u < 4; u++) {
            const int d = tx*4 + u;
            dl = fmaf(Qt[d*PADQ + row], KV[d*PADQ + row], dl);
        }
        #pragma unroll
        for (int msk = 8; msk >= 1; msk >>= 1)
            dl += __shfl_xor_sync(0xffffffffu, dl, msk);
        dl *= scale;
        const float mn   = fmaxf(m[i], dl);
        const float corr = __expf(m[i] - mn);
        const float pd   = __expf(dl   - mn);
        const float inv  = 1.0f / (l[i]*corr + pd);
        float4 xv = *(const float4*)(XVb + (size_t)(q0 + row)*DIM + tx*4);
        float4 out;
        out.x = (o[i][0]*corr + pd*xv.x) * inv;
        out.y = (o[i][1]*corr + pd*xv.y) * inv;
        out.z = (o[i][2]*corr + pd*xv.z) * inv;
        out.w = (o[i][3]*corr + pd*xv.w) * inv;
        *(float4*)(Ob + (size_t)(q0 + row)*DIM + tx*4) = out;
    }
}

// ============================================================
// Launch
// ============================================================
extern "C" void kernel_launch(void* const* d_in, const int* in_sizes, int n_in,
                              void* d_out, int out_size)
{
    const float* xq = (const float*)d_in[0];
    const float* xk = (const float*)d_in[1];
    const float* xv = (const float*)d_in[2];
    const float* Wq = (const float*)d_in[3];
    const float* Wk = (const float*)d_in[4];
    const float* Wv = (const float*)d_in[5];
    const float* Wo = (const float*)d_in[6];
    const float* bo = (const float*)d_in[7];
    float* out = (float*)d_out;

    float *Qp, *Kp, *Vp, *XKp, *XVp, *AOp;
    cudaGetSymbolAddress((void**)&Qp,  g_Q);
    cudaGetSymbolAddress((void**)&Kp,  g_K);
    cudaGetSymbolAddress((void**)&Vp,  g_V);
    cudaGetSymbolAddress((void**)&XKp, g_XK);
    cudaGetSymbolAddress((void**)&XVp, g_XV);
    cudaGetSymbolAddress((void**)&AOp, g_AO);

    const int attn_smem = (2*64*PADQ + 64*PADP) * (int)sizeof(float); // 52480 B
    cudaFuncSetAttribute(attn_kernel,
                         cudaFuncAttributeMaxDynamicSharedMemorySize, attn_smem);

    dim3 gg(DIM/GBN, MROWS/GBM);   // (8, 64)
    gemm_kernel<<<gg, 256>>>(xq, Wq, nullptr, Qp);
    gemm_kernel<<<gg, 256>>>(xk, Wk, nullptr, Kp);
    gemm_kernel<<<gg, 256>>>(xv, Wv, nullptr, Vp);
    gemm_kernel<<<gg, 256>>>(xq, Wk, nullptr, XKp);
    gemm_kernel<<<gg, 256>>>(xq, Wv, nullptr, XVp);

    dim3 ga(SEQ/64, NB*NH);        // (32, 32)
    attn_kernel<<<ga, 256, attn_smem>>>(Qp, Kp, Vp, XKp, XVp, AOp);

    gemm_kernel<<<gg, 256>>>(AOp, Wo, bo, out);
}

// round 7
// speedup vs baseline: 1.4550x; 1.4550x over previous
#include <cuda_runtime.h>
#include <cuda_bf16.h>
#include <cstdint>
#include <math.h>

#define NB   4
#define NH   8
#define SEQ  2048
#define DIM  512
#define DH   64
#define MROWS (NB*SEQ)   // 8192

// =================== scratch (static device globals) ===================
__device__ float g_Q [MROWS*DIM];
__device__ float g_K [MROWS*DIM];
__device__ float g_V [MROWS*DIM];
__device__ float g_XK[MROWS*DIM];
__device__ float g_XV[MROWS*DIM];

__device__ __align__(16) __nv_bfloat16 g_xqh[MROWS*DIM], g_xql[MROWS*DIM];
__device__ __align__(16) __nv_bfloat16 g_xkh[MROWS*DIM], g_xkl[MROWS*DIM];
__device__ __align__(16) __nv_bfloat16 g_xvh[MROWS*DIM], g_xvl[MROWS*DIM];
__device__ __align__(16) __nv_bfloat16 g_AOh[MROWS*DIM], g_AOl[MROWS*DIM];

__device__ __align__(16) __nv_bfloat16 g_WqTh[DIM*DIM], g_WqTl[DIM*DIM];
__device__ __align__(16) __nv_bfloat16 g_WkTh[DIM*DIM], g_WkTl[DIM*DIM];
__device__ __align__(16) __nv_bfloat16 g_WvTh[DIM*DIM], g_WvTl[DIM*DIM];
__device__ __align__(16) __nv_bfloat16 g_WoTh[DIM*DIM], g_WoTl[DIM*DIM];

// =================== helpers ===================
__device__ __forceinline__ uint32_t smem_u32(const void* p) {
    uint32_t a;
    asm("{ .reg .u64 t; cvta.to.shared.u64 t, %1; cvt.u32.u64 %0, t; }" : "=r"(a) : "l"(p));
    return a;
}

__device__ __forceinline__ void ldm_x4(uint32_t addr, uint32_t& r0, uint32_t& r1,
                                       uint32_t& r2, uint32_t& r3) {
    asm volatile("ldmatrix.sync.aligned.m8n8.x4.shared.b16 {%0,%1,%2,%3}, [%4];"
                 : "=r"(r0), "=r"(r1), "=r"(r2), "=r"(r3) : "r"(addr));
}

__device__ __forceinline__ void mma_bf16(float& c0, float& c1, float& c2, float& c3,
                                         uint32_t a0, uint32_t a1, uint32_t a2, uint32_t a3,
                                         uint32_t b0, uint32_t b1) {
    asm volatile(
        "mma.sync.aligned.m16n8k16.row.col.f32.bf16.bf16.f32 "
        "{%0,%1,%2,%3}, {%4,%5,%6,%7}, {%8,%9}, {%0,%1,%2,%3};"
        : "+f"(c0), "+f"(c1), "+f"(c2), "+f"(c3)
        : "r"(a0), "r"(a1), "r"(a2), "r"(a3), "r"(b0), "r"(b1));
}

__device__ __forceinline__ void bf16_split(float x, unsigned& h, unsigned& l) {
    __nv_bfloat16 bh = __float2bfloat16_rn(x);
    float r = x - __bfloat162float(bh);
    __nv_bfloat16 bl = __float2bfloat16_rn(r);
    h = (unsigned)__bfloat16_as_ushort(bh);
    l = (unsigned)__bfloat16_as_ushort(bl);
}

// =================== conversion kernels ===================
__global__ __launch_bounds__(256) void split_hl(
    const float4* __restrict__ in, uint2* __restrict__ hi, uint2* __restrict__ lo, int n4)
{
    int i = blockIdx.x * 256 + threadIdx.x;
    if (i >= n4) return;
    float4 v = in[i];
    unsigned h0,h1,h2,h3,l0,l1,l2,l3;
    bf16_split(v.x, h0, l0); bf16_split(v.y, h1, l1);
    bf16_split(v.z, h2, l2); bf16_split(v.w, h3, l3);
    hi[i] = make_uint2(h0 | (h1 << 16), h2 | (h3 << 16));
    lo[i] = make_uint2(l0 | (l1 << 16), l2 | (l3 << 16));
}

__global__ __launch_bounds__(1024) void splitT(
    const float* __restrict__ W, __nv_bfloat16* __restrict__ hiT, __nv_bfloat16* __restrict__ loT)
{
    __shared__ float t[32][33];
    const int kb = blockIdx.y * 32, nb = blockIdx.x * 32;
    const int tx = threadIdx.x, ty = threadIdx.y;
    t[ty][tx] = W[(kb + ty) * DIM + nb + tx];
    __syncthreads();
    float x = t[tx][ty];  // = W[kb+tx][nb+ty]
    unsigned h, l;
    bf16_split(x, h, l);
    hiT[(nb + ty) * DIM + kb + tx] = __ushort_as_bfloat16((unsigned short)h);
    loT[(nb + ty) * DIM + kb + tx] = __ushort_as_bfloat16((unsigned short)l);
}

// =================== HMMA GEMM: C[M,512] = A[M,512] * W (+bias) ===================
// A as bf16 hi/lo [M,512] K-major; B = W^T as bf16 hi/lo [512,512] K-major (col-major B).
// CTA tile 128x128, k-step 64, 8 warps (2m x 4n), warp tile 64x32.
#define KSTEP 64
#define SSTRIDE 72            // bf16 elements per smem row (64 + 8 pad)
#define TILE_B (128*SSTRIDE*2) // 18432 bytes per array

__global__ __launch_bounds__(256) void mma_gemm(
    const __nv_bfloat16* __restrict__ Ah, const __nv_bfloat16* __restrict__ Al,
    const __nv_bfloat16* __restrict__ Bh, const __nv_bfloat16* __restrict__ Bl,
    const float* __restrict__ bias, float* __restrict__ C)
{
    extern __shared__ __align__(16) __nv_bfloat16 sm[];
    __nv_bfloat16* sAh = sm;
    __nv_bfloat16* sAl = sm + 128*SSTRIDE;
    __nv_bfloat16* sBh = sm + 2*128*SSTRIDE;
    __nv_bfloat16* sBl = sm + 3*128*SSTRIDE;

    const int tid  = threadIdx.x;
    const int wid  = tid >> 5;
    const int lane = tid & 31;
    const int bm = blockIdx.y * 128;
    const int bn = blockIdx.x * 128;
    const int wm = (wid & 1) * 64;     // warp m offset (0/64)
    const int wn = (wid >> 1) * 32;    // warp n offset (0/32/64/96)

    // ldmatrix per-lane element offsets (in bf16 elements)
    const int aOff = (wm + (lane & 15)) * SSTRIDE + (lane >> 4) * 8;
    const int bn_local = ((lane >> 4) & 1) * 8 + (lane & 7);
    const int bk_local = ((lane >> 3) & 1) * 8;
    const int bOff = (wn + bn_local) * SSTRIDE + bk_local;

    const uint32_t sb   = smem_u32(sm);
    const uint32_t aHi  = sb + aOff * 2;
    const uint32_t aLo  = aHi + TILE_B;
    const uint32_t bHi  = sb + 2 * TILE_B + bOff * 2;
    const uint32_t bLo  = bHi + TILE_B;

    float acc[4][4][4];
    #pragma unroll
    for (int i = 0; i < 4; i++)
        #pragma unroll
        for (int j = 0; j < 4; j++)
            #pragma unroll
            for (int r = 0; r < 4; r++) acc[i][j][r] = 0.f;

    const int lrow = tid >> 3;        // 0..31 (row group base)
    const int lseg = (tid & 7) * 8;   // bf16 column 0..56

    for (int k0 = 0; k0 < DIM; k0 += KSTEP) {
        __syncthreads();
        // load 4 tiles [128][64] bf16 (each thread: 4 rows x 1 seg per array)
        #pragma unroll
        for (int it = 0; it < 4; it++) {
            const int row = lrow + it * 32;
            const size_t ga = (size_t)(bm + row) * DIM + k0 + lseg;
            const size_t gb = (size_t)(bn + row) * DIM + k0 + lseg;
            const int so = row * SSTRIDE + lseg;
            *(uint4*)&sAh[so] = *(const uint4*)(Ah + ga);
            *(uint4*)&sAl[so] = *(const uint4*)(Al + ga);
            *(uint4*)&sBh[so] = *(const uint4*)(Bh + gb);
            *(uint4*)&sBl[so] = *(const uint4*)(Bl + gb);
        }
        __syncthreads();

        #pragma unroll
        for (int kk = 0; kk < KSTEP / 16; kk++) {
            const uint32_t kb = kk * 32;   // 16 bf16 = 32 bytes
            uint32_t ah[4][4], al[4][4], bh[4][2], bl[4][2];
            #pragma unroll
            for (int nt = 0; nt < 2; nt++) {
                const uint32_t adr = nt * (16 * SSTRIDE * 2) + kb;
                ldm_x4(bHi + adr, bh[nt*2][0], bh[nt*2][1], bh[nt*2+1][0], bh[nt*2+1][1]);
                ldm_x4(bLo + adr, bl[nt*2][0], bl[nt*2][1], bl[nt*2+1][0], bl[nt*2+1][1]);
            }
            #pragma unroll
            for (int mt = 0; mt < 4; mt++) {
                const uint32_t adr = mt * (16 * SSTRIDE * 2) + kb;
                ldm_x4(aHi + adr, ah[mt][0], ah[mt][1], ah[mt][2], ah[mt][3]);
                ldm_x4(aLo + adr, al[mt][0], al[mt][1], al[mt][2], al[mt][3]);
            }
            #pragma unroll
            for (int mt = 0; mt < 4; mt++)
                #pragma unroll
                for (int nt = 0; nt < 4; nt++) {
                    mma_bf16(acc[mt][nt][0], acc[mt][nt][1], acc[mt][nt][2], acc[mt][nt][3],
                             ah[mt][0], ah[mt][1], ah[mt][2], ah[mt][3],
                             bh[nt][0], bh[nt][1]);
                    mma_bf16(acc[mt][nt][0], acc[mt][nt][1], acc[mt][nt][2], acc[mt][nt][3],
                             ah[mt][0], ah[mt][1], ah[mt][2], ah[mt][3],
                             bl[nt][0], bl[nt][1]);
                    mma_bf16(acc[mt][nt][0], acc[mt][nt][1], acc[mt][nt][2], acc[mt][nt][3],
                             al[mt][0], al[mt][1], al[mt][2], al[mt][3],
                             bh[nt][0], bh[nt][1]);
                }
        }
    }

    // epilogue
    const int er = lane >> 2;          // 0..7
    const int ec = (lane & 3) * 2;     // 0..6
    #pragma unroll
    for (int mt = 0; mt < 4; mt++) {
        #pragma unroll
        for (int nt = 0; nt < 4; nt++) {
            const int col = bn + wn + nt * 8 + ec;
            float b0 = 0.f, b1 = 0.f;
            if (bias) { b0 = bias[col]; b1 = bias[col + 1]; }
            const int r0 = bm + wm + mt * 16 + er;
            float2 v0 = make_float2(acc[mt][nt][0] + b0, acc[mt][nt][1] + b1);
            float2 v1 = make_float2(acc[mt][nt][2] + b0, acc[mt][nt][3] + b1);
            *(float2*)(C + (size_t)r0 * DIM + col)       = v0;
            *(float2*)(C + (size_t)(r0 + 8) * DIM + col) = v1;
        }
    }
}

// =================== flash attention (q-tile 128, 8x4 fragments) ===================
#define PADQ 132
#define PADK 68

__global__ __launch_bounds__(256, 2) void attn_kernel(
    const float* __restrict__ Q,  const float* __restrict__ K,
    const float* __restrict__ V,  const float* __restrict__ XK,
    const float* __restrict__ XV,
    __nv_bfloat16* __restrict__ AOh, __nv_bfloat16* __restrict__ AOl)
{
    extern __shared__ float smf[];
    float* Qt = smf;                    // [64][PADQ]  Qt[d][q]
    float* KV = smf + 64*PADQ;          // [64][PADK]  Kt[d][kv] then V[kv][dh]
    float* Ps = smf + 64*PADQ + 64*PADK;// [128][PADK] P[q][kv]; reused as XKt[d][q]

    const int tid = threadIdx.x;
    const int tx  = tid & 15;
    const int ty  = tid >> 4;
    const int b   = blockIdx.y >> 3;
    const int h   = blockIdx.y & 7;
    const int q0  = blockIdx.x * 128;
    const float scale = 0.125f;

    const float* Qb  = Q  + ((size_t)b*SEQ)*DIM + h*DH;
    const float* Kb  = K  + ((size_t)b*SEQ)*DIM + h*DH;
    const float* Vb  = V  + ((size_t)b*SEQ)*DIM + h*DH;
    const float* XKb = XK + ((size_t)b*SEQ)*DIM + h*DH;
    const float* XVb = XV + ((size_t)b*SEQ)*DIM + h*DH;

    const int lr = tid >> 4;
    const int lc = (tid & 15) * 4;

    #pragma unroll
    for (int it = 0; it < 8; it++) {
        const int r = lr + it*16;
        float4 v = *(const float4*)(Qb + (size_t)(q0 + r)*DIM + lc);
        Qt[(lc+0)*PADQ + r] = v.x;
        Qt[(lc+1)*PADQ + r] = v.y;
        Qt[(lc+2)*PADQ + r] = v.z;
        Qt[(lc+3)*PADQ + r] = v.w;
    }

    float m[8], l[8], o[8][4];
    #pragma unroll
    for (int i = 0; i < 8; i++) {
        m[i] = -1e30f; l[i] = 0.f;
        #pragma unroll
        for (int j = 0; j < 4; j++) o[i][j] = 0.f;
    }

    for (int t = 0; t < SEQ/64; t++) {
        __syncthreads();
        #pragma unroll
        for (int it = 0; it < 4; it++) {
            const int r = lr + it*16;
            float4 v = *(const float4*)(Kb + (size_t)(t*64 + r)*DIM + lc);
            KV[(lc+0)*PADK + r] = v.x;
            KV[(lc+1)*PADK + r] = v.y;
            KV[(lc+2)*PADK + r] = v.z;
            KV[(lc+3)*PADK + r] = v.w;
        }
        __syncthreads();

        float s[8][4];
        #pragma unroll
        for (int i = 0; i < 8; i++)
            #pragma unroll
            for (int j = 0; j < 4; j++) s[i][j] = 0.f;
        #pragma unroll 4
        for (int d = 0; d < 64; d++) {
            float4 qa = *(const float4*)&Qt[d*PADQ + ty*8];
            float4 qb = *(const float4*)&Qt[d*PADQ + ty*8 + 4];
            float4 ka = *(const float4*)&KV[d*PADK + tx*4];
            float qr[8] = {qa.x,qa.y,qa.z,qa.w,qb.x,qb.y,qb.z,qb.w};
            float kr[4] = {ka.x,ka.y,ka.z,ka.w};
            #pragma unroll
            for (int i = 0; i < 8; i++)
                #pragma unroll
                for (int j = 0; j < 4; j++)
                    s[i][j] = fmaf(qr[i], kr[j], s[i][j]);
        }

        #pragma unroll
        for (int i = 0; i < 8; i++) {
            #pragma unroll
            for (int j = 0; j < 4; j++) s[i][j] *= scale;
            float rm = fmaxf(fmaxf(s[i][0], s[i][1]), fmaxf(s[i][2], s[i][3]));
            #pragma unroll
            for (int msk = 8; msk >= 1; msk >>= 1)
                rm = fmaxf(rm, __shfl_xor_sync(0xffffffffu, rm, msk));
            const float mn   = fmaxf(m[i], rm);
            const float corr = __expf(m[i] - mn);
            float p[4], ps = 0.f;
            #pragma unroll
            for (int j = 0; j < 4; j++) { p[j] = __expf(s[i][j] - mn); ps += p[j]; }
            #pragma unroll
            for (int msk = 8; msk >= 1; msk >>= 1)
                ps += __shfl_xor_sync(0xffffffffu, ps, msk);
            l[i] = l[i]*corr + ps;
            m[i] = mn;
            #pragma unroll
            for (int j = 0; j < 4; j++) o[i][j] *= corr;
            *(float4*)&Ps[(ty*8 + i)*PADK + tx*4] = make_float4(p[0], p[1], p[2], p[3]);
        }
        __syncthreads();

        #pragma unroll
        for (int it = 0; it < 4; it++) {
            const int r = lr + it*16;
            *(float4*)&KV[r*PADK + lc] = *(const float4*)(Vb + (size_t)(t*64 + r)*DIM + lc);
        }
        __syncthreads();

        #pragma unroll 4
        for (int kv = 0; kv < 64; kv++) {
            float4 bv = *(const float4*)&KV[kv*PADK + tx*4];
            float br[4] = {bv.x, bv.y, bv.z, bv.w};
            #pragma unroll
            for (int i = 0; i < 8; i++) {
                const float pv = Ps[(ty*8 + i)*PADK + kv];
                #pragma unroll
                for (int j = 0; j < 4; j++)
                    o[i][j] = fmaf(pv, br[j], o[i][j]);
            }
        }
    }

    // ---- diagonal term ----
    __syncthreads();
    #pragma unroll
    for (int it = 0; it < 8; it++) {
        const int r = lr + it*16;
        float4 v = *(const float4*)(XKb + (size_t)(q0 + r)*DIM + lc);
        Ps[(lc+0)*PADQ + r] = v.x;
        Ps[(lc+1)*PADQ + r] = v.y;
        Ps[(lc+2)*PADQ + r] = v.z;
        Ps[(lc+3)*PADQ + r] = v.w;
    }
    __syncthreads();

    #pragma unroll
    for (int i = 0; i < 8; i++) {
        const int row = ty*8 + i;
        float dl = 0.f;
        #pragma unroll
        for (int u = 0; u < 4; u++) {
            const int d = tx*4 + u;
            dl = fmaf(Qt[d*PADQ + row], Ps[d*PADQ + row], dl);
        }
        #pragma unroll
        for (int msk = 8; msk >= 1; msk >>= 1)
            dl += __shfl_xor_sync(0xffffffffu, dl, msk);
        dl *= scale;
        const float mn   = fmaxf(m[i], dl);
        const float corr = __expf(m[i] - mn);
        const float pd   = __expf(dl   - mn);
        const float inv  = 1.0f / (l[i]*corr + pd);
        float4 xv = *(const float4*)(XVb + (size_t)(q0 + row)*DIM + tx*4);
        float ox = (o[i][0]*corr + pd*xv.x) * inv;
        float oy = (o[i][1]*corr + pd*xv.y) * inv;
        float oz = (o[i][2]*corr + pd*xv.z) * inv;
        float ow = (o[i][3]*corr + pd*xv.w) * inv;
        unsigned h0,h1,h2,h3,l0,l1,l2,l3;
        bf16_split(ox, h0, l0); bf16_split(oy, h1, l1);
        bf16_split(oz, h2, l2); bf16_split(ow, h3, l3);
        // FIX: include batch offset b*SEQ in the output row index
        const size_t e = ((size_t)(b*SEQ + q0 + row))*DIM + h*DH + tx*4;
        *(uint2*)(AOh + e) = make_uint2(h0 | (h1 << 16), h2 | (h3 << 16));
        *(uint2*)(AOl + e) = make_uint2(l0 | (l1 << 16), l2 | (l3 << 16));
    }
}

// =================== launch ===================
extern "C" void kernel_launch(void* const* d_in, const int* in_sizes, int n_in,
                              void* d_out, int out_size)
{
    const float* xq = (const float*)d_in[0];
    const float* xk = (const float*)d_in[1];
    const float* xv = (const float*)d_in[2];
    const float* Wq = (const float*)d_in[3];
    const float* Wk = (const float*)d_in[4];
    const float* Wv = (const float*)d_in[5];
    const float* Wo = (const float*)d_in[6];
    const float* bo = (const float*)d_in[7];
    float* out = (float*)d_out;

    float *Qp, *Kp, *Vp, *XKp, *XVp;
    cudaGetSymbolAddress((void**)&Qp,  g_Q);
    cudaGetSymbolAddress((void**)&Kp,  g_K);
    cudaGetSymbolAddress((void**)&Vp,  g_V);
    cudaGetSymbolAddress((void**)&XKp, g_XK);
    cudaGetSymbolAddress((void**)&XVp, g_XV);

    __nv_bfloat16 *xqh,*xql,*xkh,*xkl,*xvh,*xvl,*aoh,*aol;
    __nv_bfloat16 *wqh,*wql,*wkh,*wkl,*wvh,*wvl,*woh,*wol;
    cudaGetSymbolAddress((void**)&xqh, g_xqh); cudaGetSymbolAddress((void**)&xql, g_xql);
    cudaGetSymbolAddress((void**)&xkh, g_xkh); cudaGetSymbolAddress((void**)&xkl, g_xkl);
    cudaGetSymbolAddress((void**)&xvh, g_xvh); cudaGetSymbolAddress((void**)&xvl, g_xvl);
    cudaGetSymbolAddress((void**)&aoh, g_AOh); cudaGetSymbolAddress((void**)&aol, g_AOl);
    cudaGetSymbolAddress((void**)&wqh, g_WqTh); cudaGetSymbolAddress((void**)&wql, g_WqTl);
    cudaGetSymbolAddress((void**)&wkh, g_WkTh); cudaGetSymbolAddress((void**)&wkl, g_WkTl);
    cudaGetSymbolAddress((void**)&wvh, g_WvTh); cudaGetSymbolAddress((void**)&wvl, g_WvTl);
    cudaGetSymbolAddress((void**)&woh, g_WoTh); cudaGetSymbolAddress((void**)&wol, g_WoTl);

    const int gemm_smem = 4 * TILE_B;                           // 73728
    const int attn_smem = (64*PADQ + 64*PADK + 128*PADK) * 4;   // 86016
    cudaFuncSetAttribute(mma_gemm,
                         cudaFuncAttributeMaxDynamicSharedMemorySize, gemm_smem);
    cudaFuncSetAttribute(attn_kernel,
                         cudaFuncAttributeMaxDynamicSharedMemorySize, attn_smem);

    // ---- conversions ----
    const int n4 = MROWS*DIM/4;
    split_hl<<<n4/256, 256>>>((const float4*)xq, (uint2*)xqh, (uint2*)xql, n4);
    split_hl<<<n4/256, 256>>>((const float4*)xk, (uint2*)xkh, (uint2*)xkl, n4);
    split_hl<<<n4/256, 256>>>((const float4*)xv, (uint2*)xvh, (uint2*)xvl, n4);
    dim3 tgrid(DIM/32, DIM/32), tblk(32, 32);
    splitT<<<tgrid, tblk>>>(Wq, wqh, wql);
    splitT<<<tgrid, tblk>>>(Wk, wkh, wkl);
    splitT<<<tgrid, tblk>>>(Wv, wvh, wvl);
    splitT<<<tgrid, tblk>>>(Wo, woh, wol);

    // ---- projection GEMMs (HMMA) ----
    dim3 gg(DIM/128, MROWS/128);   // (4, 64)
    mma_gemm<<<gg, 256, gemm_smem>>>(xqh, xql, wqh, wql, nullptr, Qp);
    mma_gemm<<<gg, 256, gemm_smem>>>(xkh, xkl, wkh, wkl, nullptr, Kp);
    mma_gemm<<<gg, 256, gemm_smem>>>(xvh, xvl, wvh, wvl, nullptr, Vp);
    mma_gemm<<<gg, 256, gemm_smem>>>(xqh, xql, wkh, wkl, nullptr, XKp);
    mma_gemm<<<gg, 256, gemm_smem>>>(xqh, xql, wvh, wvl, nullptr, XVp);

    // ---- attention ----
    dim3 ga(SEQ/128, NB*NH);       // (16, 32)
    attn_kernel<<<ga, 256, attn_smem>>>(Qp, Kp, Vp, XKp, XVp, aoh, aol);

    // ---- output GEMM (+bias) ----
    mma_gemm<<<gg, 256, gemm_smem>>>(aoh, aol, woh, wol, bo, out);
}

// round 10
// speedup vs baseline: 1.4678x; 1.0087x over previous
#include <cuda_runtime.h>
#include <cuda_bf16.h>
#include <cstdint>
#include <math.h>

#define NB   4
#define NH   8
#define SEQ  2048
#define DIM  512
#define DH   64
#define MROWS (NB*SEQ)   // 8192

// =================== scratch (static device globals) ===================
__device__ float g_Q [MROWS*DIM];
__device__ float g_K [MROWS*DIM];
__device__ float g_V [MROWS*DIM];
__device__ float g_XK[MROWS*DIM];
__device__ float g_XV[MROWS*DIM];

__device__ __align__(16) __nv_bfloat16 g_xqh[MROWS*DIM], g_xql[MROWS*DIM];
__device__ __align__(16) __nv_bfloat16 g_xkh[MROWS*DIM], g_xkl[MROWS*DIM];
__device__ __align__(16) __nv_bfloat16 g_xvh[MROWS*DIM], g_xvl[MROWS*DIM];
__device__ __align__(16) __nv_bfloat16 g_AOh[MROWS*DIM], g_AOl[MROWS*DIM];

__device__ __align__(16) __nv_bfloat16 g_WqTh[DIM*DIM], g_WqTl[DIM*DIM];
__device__ __align__(16) __nv_bfloat16 g_WkTh[DIM*DIM], g_WkTl[DIM*DIM];
__device__ __align__(16) __nv_bfloat16 g_WvTh[DIM*DIM], g_WvTl[DIM*DIM];
__device__ __align__(16) __nv_bfloat16 g_WoTh[DIM*DIM], g_WoTl[DIM*DIM];

// =================== helpers ===================
__device__ __forceinline__ uint32_t smem_u32(const void* p) {
    uint32_t a;
    asm("{ .reg .u64 t; cvta.to.shared.u64 t, %1; cvt.u32.u64 %0, t; }" : "=r"(a) : "l"(p));
    return a;
}

__device__ __forceinline__ void ldm_x4(uint32_t addr, uint32_t& r0, uint32_t& r1,
                                       uint32_t& r2, uint32_t& r3) {
    asm volatile("ldmatrix.sync.aligned.m8n8.x4.shared.b16 {%0,%1,%2,%3}, [%4];"
                 : "=r"(r0), "=r"(r1), "=r"(r2), "=r"(r3) : "r"(addr));
}

__device__ __forceinline__ void mma_bf16(float& c0, float& c1, float& c2, float& c3,
                                         uint32_t a0, uint32_t a1, uint32_t a2, uint32_t a3,
                                         uint32_t b0, uint32_t b1) {
    asm volatile(
        "mma.sync.aligned.m16n8k16.row.col.f32.bf16.bf16.f32 "
        "{%0,%1,%2,%3}, {%4,%5,%6,%7}, {%8,%9}, {%0,%1,%2,%3};"
        : "+f"(c0), "+f"(c1), "+f"(c2), "+f"(c3)
        : "r"(a0), "r"(a1), "r"(a2), "r"(a3), "r"(b0), "r"(b1));
}

__device__ __forceinline__ void cp16(uint32_t dst, const void* src) {
    asm volatile("cp.async.cg.shared.global [%0], [%1], 16;" :: "r"(dst), "l"(src));
}
__device__ __forceinline__ void cp_commit() {
    asm volatile("cp.async.commit_group;");
}
template<int N> __device__ __forceinline__ void cp_wait() {
    asm volatile("cp.async.wait_group %0;" :: "n"(N));
}

__device__ __forceinline__ void bf16_split(float x, unsigned& h, unsigned& l) {
    __nv_bfloat16 bh = __float2bfloat16_rn(x);
    float r = x - __bfloat162float(bh);
    __nv_bfloat16 bl = __float2bfloat16_rn(r);
    h = (unsigned)__bfloat16_as_ushort(bh);
    l = (unsigned)__bfloat16_as_ushort(bl);
}

// =================== conversion kernels ===================
__global__ __launch_bounds__(256) void split_hl(
    const float4* __restrict__ in, uint2* __restrict__ hi, uint2* __restrict__ lo, int n4)
{
    int i = blockIdx.x * 256 + threadIdx.x;
    if (i >= n4) return;
    float4 v = in[i];
    unsigned h0,h1,h2,h3,l0,l1,l2,l3;
    bf16_split(v.x, h0, l0); bf16_split(v.y, h1, l1);
    bf16_split(v.z, h2, l2); bf16_split(v.w, h3, l3);
    hi[i] = make_uint2(h0 | (h1 << 16), h2 | (h3 << 16));
    lo[i] = make_uint2(l0 | (l1 << 16), l2 | (l3 << 16));
}

__global__ __launch_bounds__(1024) void splitT(
    const float* __restrict__ W, __nv_bfloat16* __restrict__ hiT, __nv_bfloat16* __restrict__ loT)
{
    __shared__ float t[32][33];
    const int kb = blockIdx.y * 32, nb = blockIdx.x * 32;
    const int tx = threadIdx.x, ty = threadIdx.y;
    t[ty][tx] = W[(kb + ty) * DIM + nb + tx];
    __syncthreads();
    float x = t[tx][ty];  // = W[kb+tx][nb+ty]
    unsigned h, l;
    bf16_split(x, h, l);
    hiT[(nb + ty) * DIM + kb + tx] = __ushort_as_bfloat16((unsigned short)h);
    loT[(nb + ty) * DIM + kb + tx] = __ushort_as_bfloat16((unsigned short)l);
}

// =================== HMMA GEMM v2: C[M,512] = A[M,512] * W (+bias) ===================
// CTA tile 128x256, KSTEP 32, cp.async double buffer, 8 warps, warp tile 64x64.
// smem row stride 40 bf16 (80B) -> ldmatrix conflict-free (80k mod 128 distinct).
#define KST   32
#define SSTR  40                     // bf16 elements per smem row
#define A_EL  (128*SSTR)             // 5120 elements
#define B_EL  (256*SSTR)             // 10240 elements
#define STAGE_EL (2*A_EL + 2*B_EL)   // 30720 elements
#define STAGE_B  (STAGE_EL*2)        // 61440 bytes

__global__ __launch_bounds__(256) void mma_gemm(
    const __nv_bfloat16* __restrict__ Ah, const __nv_bfloat16* __restrict__ Al,
    const __nv_bfloat16* __restrict__ Bh, const __nv_bfloat16* __restrict__ Bl,
    const float* __restrict__ bias, float* __restrict__ C)
{
    extern __shared__ __align__(16) __nv_bfloat16 sm[];

    const int tid  = threadIdx.x;
    const int wid  = tid >> 5;
    const int lane = tid & 31;
    const int bm = blockIdx.y * 128;
    const int bn = blockIdx.x * 256;
    const int wm = (wid & 1) * 64;     // warp m offset (0/64)
    const int wn = (wid >> 1) * 64;    // warp n offset (0/64/128/192)

    const uint32_t sb = smem_u32(sm);

    // fragment lane offsets (bytes)
    const int aOff = ((wm + (lane & 15)) * SSTR + (lane >> 4) * 8) * 2;
    const int bn_local = ((lane >> 4) & 1) * 8 + (lane & 7);
    const int bk_local = ((lane >> 3) & 1) * 8;
    const int bOff = ((wn + bn_local) * SSTR + bk_local) * 2;

    // loader: lrow = tid>>2 (0..63), lseg = (tid&3)*8
    const int lrow = tid >> 2;
    const int lsege = (tid & 3) * 8;          // element col
    const uint32_t lso = (uint32_t)(lrow * SSTR + lsege) * 2;  // smem byte offset within array

    auto prefetch = [&](int j) {
        const int k0 = j * KST;
        const uint32_t st = sb + (j & 1) * STAGE_B;
        #pragma unroll
        for (int it = 0; it < 2; it++) {
            const int row = lrow + it * 64;
            const size_t g = (size_t)(bm + row) * DIM + k0 + lsege;
            const uint32_t d = st + (uint32_t)(it * 64 * SSTR * 2) + lso;
            cp16(d,              Ah + g);
            cp16(d + A_EL * 2,   Al + g);
        }
        #pragma unroll
        for (int it = 0; it < 4; it++) {
            const int row = lrow + it * 64;
            const size_t g = (size_t)(bn + row) * DIM + k0 + lsege;
            const uint32_t d = st + (uint32_t)(2 * A_EL * 2) + (uint32_t)(it * 64 * SSTR * 2) + lso;
            cp16(d,              Bh + g);
            cp16(d + B_EL * 2,   Bl + g);
        }
    };

    float acc[4][8][4];
    #pragma unroll
    for (int i = 0; i < 4; i++)
        #pragma unroll
        for (int j = 0; j < 8; j++)
            #pragma unroll
            for (int r = 0; r < 4; r++) acc[i][j][r] = 0.f;

    prefetch(0);
    cp_commit();

    for (int j = 0; j < DIM / KST; j++) {
        if (j + 1 < DIM / KST) {
            prefetch(j + 1);
            cp_commit();
            cp_wait<1>();
        } else {
            cp_wait<0>();
        }
        __syncthreads();

        const uint32_t st  = sb + (j & 1) * STAGE_B;
        const uint32_t aHi = st + aOff;
        const uint32_t aLo = aHi + A_EL * 2;
        const uint32_t bHi = st + 2 * A_EL * 2 + bOff;
        const uint32_t bLo = bHi + B_EL * 2;

        #pragma unroll
        for (int kk = 0; kk < KST / 16; kk++) {
            const uint32_t kb = kk * 32;   // 16 bf16 = 32 bytes
            uint32_t ah[4][4], al[4][4];
            #pragma unroll
            for (int mt = 0; mt < 4; mt++) {
                const uint32_t adr = mt * (16 * SSTR * 2) + kb;
                ldm_x4(aHi + adr, ah[mt][0], ah[mt][1], ah[mt][2], ah[mt][3]);
                ldm_x4(aLo + adr, al[mt][0], al[mt][1], al[mt][2], al[mt][3]);
            }
            #pragma unroll
            for (int h = 0; h < 2; h++) {
                uint32_t bh4[4][2], bl4[4][2];
                #pragma unroll
                for (int p = 0; p < 2; p++) {
                    const uint32_t adr = (h * 2 + p) * (16 * SSTR * 2) + kb;
                    ldm_x4(bHi + adr, bh4[p*2][0], bh4[p*2][1], bh4[p*2+1][0], bh4[p*2+1][1]);
                    ldm_x4(bLo + adr, bl4[p*2][0], bl4[p*2][1], bl4[p*2+1][0], bl4[p*2+1][1]);
                }
                #pragma unroll
                for (int mt = 0; mt < 4; mt++)
                    #pragma unroll
                    for (int q = 0; q < 4; q++) {
                        float* a = acc[mt][h*4 + q];
                        mma_bf16(a[0], a[1], a[2], a[3],
                                 ah[mt][0], ah[mt][1], ah[mt][2], ah[mt][3],
                                 bh4[q][0], bh4[q][1]);
                        mma_bf16(a[0], a[1], a[2], a[3],
                                 ah[mt][0], ah[mt][1], ah[mt][2], ah[mt][3],
                                 bl4[q][0], bl4[q][1]);
                        mma_bf16(a[0], a[1], a[2], a[3],
                                 al[mt][0], al[mt][1], al[mt][2], al[mt][3],
                                 bh4[q][0], bh4[q][1]);
                    }
            }
        }
        __syncthreads();
    }

    // epilogue
    const int er = lane >> 2;          // 0..7
    const int ec = (lane & 3) * 2;     // 0..6
    #pragma unroll
    for (int mt = 0; mt < 4; mt++) {
        #pragma unroll
        for (int nt = 0; nt < 8; nt++) {
            const int col = bn + wn + nt * 8 + ec;
            float b0 = 0.f, b1 = 0.f;
            if (bias) { b0 = bias[col]; b1 = bias[col + 1]; }
            const int r0 = bm + wm + mt * 16 + er;
            float2 v0 = make_float2(acc[mt][nt][0] + b0, acc[mt][nt][1] + b1);
            float2 v1 = make_float2(acc[mt][nt][2] + b0, acc[mt][nt][3] + b1);
            *(float2*)(C + (size_t)r0 * DIM + col)       = v0;
            *(float2*)(C + (size_t)(r0 + 8) * DIM + col) = v1;
        }
    }
}

// =================== flash attention (q-tile 128, 8x4 fragments) ===================
#define PADQ 132
#define PADK 68

__global__ __launch_bounds__(256, 2) void attn_kernel(
    const float* __restrict__ Q,  const float* __restrict__ K,
    const float* __restrict__ V,  const float* __restrict__ XK,
    const float* __restrict__ XV,
    __nv_bfloat16* __restrict__ AOh, __nv_bfloat16* __restrict__ AOl)
{
    extern __shared__ float smf[];
    float* Qt = smf;                    // [64][PADQ]  Qt[d][q]
    float* KV = smf + 64*PADQ;          // [64][PADK]  Kt[d][kv] then V[kv][dh]
    float* Ps = smf + 64*PADQ + 64*PADK;// [128][PADK] P[q][kv]; reused as XKt[d][q]

    const int tid = threadIdx.x;
    const int tx  = tid & 15;
    const int ty  = tid >> 4;
    const int b   = blockIdx.y >> 3;
    const int h   = blockIdx.y & 7;
    const int q0  = blockIdx.x * 128;
    const float scale = 0.125f;

    const float* Qb  = Q  + ((size_t)b*SEQ)*DIM + h*DH;
    const float* Kb  = K  + ((size_t)b*SEQ)*DIM + h*DH;
    const float* Vb  = V  + ((size_t)b*SEQ)*DIM + h*DH;
    const float* XKb = XK + ((size_t)b*SEQ)*DIM + h*DH;
    const float* XVb = XV + ((size_t)b*SEQ)*DIM + h*DH;

    const int lr = tid >> 4;
    const int lc = (tid & 15) * 4;

    #pragma unroll
    for (int it = 0; it < 8; it++) {
        const int r = lr + it*16;
        float4 v = *(const float4*)(Qb + (size_t)(q0 + r)*DIM + lc);
        Qt[(lc+0)*PADQ + r] = v.x;
        Qt[(lc+1)*PADQ + r] = v.y;
        Qt[(lc+2)*PADQ + r] = v.z;
        Qt[(lc+3)*PADQ + r] = v.w;
    }

    float m[8], l[8], o[8][4];
    #pragma unroll
    for (int i = 0; i < 8; i++) {
        m[i] = -1e30f; l[i] = 0.f;
        #pragma unroll
        for (int j = 0; j < 4; j++) o[i][j] = 0.f;
    }

    for (int t = 0; t < SEQ/64; t++) {
        __syncthreads();
        #pragma unroll
        for (int it = 0; it < 4; it++) {
            const int r = lr + it*16;
            float4 v = *(const float4*)(Kb + (size_t)(t*64 + r)*DIM + lc);
            KV[(lc+0)*PADK + r] = v.x;
            KV[(lc+1)*PADK + r] = v.y;
            KV[(lc+2)*PADK + r] = v.z;
            KV[(lc+3)*PADK + r] = v.w;
        }
        __syncthreads();

        float s[8][4];
        #pragma unroll
        for (int i = 0; i < 8; i++)
            #pragma unroll
            for (int j = 0; j < 4; j++) s[i][j] = 0.f;
        #pragma unroll 4
        for (int d = 0; d < 64; d++) {
            float4 qa = *(const float4*)&Qt[d*PADQ + ty*8];
            float4 qb = *(const float4*)&Qt[d*PADQ + ty*8 + 4];
            float4 ka = *(const float4*)&KV[d*PADK + tx*4];
            float qr[8] = {qa.x,qa.y,qa.z,qa.w,qb.x,qb.y,qb.z,qb.w};
            float kr[4] = {ka.x,ka.y,ka.z,ka.w};
            #pragma unroll
            for (int i = 0; i < 8; i++)
                #pragma unroll
                for (int j = 0; j < 4; j++)
                    s[i][j] = fmaf(qr[i], kr[j], s[i][j]);
        }

        #pragma unroll
        for (int i = 0; i < 8; i++) {
            #pragma unroll
            for (int j = 0; j < 4; j++) s[i][j] *= scale;
            float rm = fmaxf(fmaxf(s[i][0], s[i][1]), fmaxf(s[i][2], s[i][3]));
            #pragma unroll
            for (int msk = 8; msk >= 1; msk >>= 1)
                rm = fmaxf(rm, __shfl_xor_sync(0xffffffffu, rm, msk));
            const float mn   = fmaxf(m[i], rm);
            const float corr = __expf(m[i] - mn);
            float p[4], ps = 0.f;
            #pragma unroll
            for (int j = 0; j < 4; j++) { p[j] = __expf(s[i][j] - mn); ps += p[j]; }
            #pragma unroll
            for (int msk = 8; msk >= 1; msk >>= 1)
                ps += __shfl_xor_sync(0xffffffffu, ps, msk);
            l[i] = l[i]*corr + ps;
            m[i] = mn;
            #pragma unroll
            for (int j = 0; j < 4; j++) o[i][j] *= corr;
            *(float4*)&Ps[(ty*8 + i)*PADK + tx*4] = make_float4(p[0], p[1], p[2], p[3]);
        }
        __syncthreads();

        #pragma unroll
        for (int it = 0; it < 4; it++) {
            const int r = lr + it*16;
            *(float4*)&KV[r*PADK + lc] = *(const float4*)(Vb + (size_t)(t*64 + r)*DIM + lc);
        }
        __syncthreads();

        // O += P V  (kv chunked by 4, float4 P loads)
        #pragma unroll 2
        for (int kv = 0; kv < 64; kv += 4) {
            float4 b0 = *(const float4*)&KV[(kv+0)*PADK + tx*4];
            float4 b1 = *(const float4*)&KV[(kv+1)*PADK + tx*4];
            float4 b2 = *(const float4*)&KV[(kv+2)*PADK + tx*4];
            float4 b3 = *(const float4*)&KV[(kv+3)*PADK + tx*4];
            #pragma unroll
            for (int i = 0; i < 8; i++) {
                float4 p = *(const float4*)&Ps[(ty*8 + i)*PADK + kv];
                o[i][0] = fmaf(p.x, b0.x, fmaf(p.y, b1.x, fmaf(p.z, b2.x, fmaf(p.w, b3.x, o[i][0]))));
                o[i][1] = fmaf(p.x, b0.y, fmaf(p.y, b1.y, fmaf(p.z, b2.y, fmaf(p.w, b3.y, o[i][1]))));
                o[i][2] = fmaf(p.x, b0.z, fmaf(p.y, b1.z, fmaf(p.z, b2.z, fmaf(p.w, b3.z, o[i][2]))));
                o[i][3] = fmaf(p.x, b0.w, fmaf(p.y, b1.w, fmaf(p.z, b2.w, fmaf(p.w, b3.w, o[i][3]))));
            }
        }
    }

    // ---- diagonal term ----
    __syncthreads();
    #pragma unroll
    for (int it = 0; it < 8; it++) {
        const int r = lr + it*16;
        float4 v = *(const float4*)(XKb + (size_t)(q0 + r)*DIM + lc);
        Ps[(lc+0)*PADQ + r] = v.x;
        Ps[(lc+1)*PADQ + r] = v.y;
        Ps[(lc+2)*PADQ + r] = v.z;
        Ps[(lc+3)*PADQ + r] = v.w;
    }
    __syncthreads();

    #pragma unroll
    for (int i = 0; i < 8; i++) {
        const int row = ty*8 + i;
        float dl = 0.f;
        #pragma unroll
        for (int u = 0; u < 4; u++) {
            const int d = tx*4 + u;
            dl = fmaf(Qt[d*PADQ + row], Ps[d*PADQ + row], dl);
        }
        #pragma unroll
        for (int msk = 8; msk >= 1; msk >>= 1)
            dl += __shfl_xor_sync(0xffffffffu, dl, msk);
        dl *= scale;
        const float mn   = fmaxf(m[i], dl);
        const float corr = __expf(m[i] - mn);
        const float pd   = __expf(dl   - mn);
        const float inv  = 1.0f / (l[i]*corr + pd);
        float4 xv = *(const float4*)(XVb + (size_t)(q0 + row)*DIM + tx*4);
        float ox = (o[i][0]*corr + pd*xv.x) * inv;
        float oy = (o[i][1]*corr + pd*xv.y) * inv;
        float oz = (o[i][2]*corr + pd*xv.z) * inv;
        float ow = (o[i][3]*corr + pd*xv.w) * inv;
        unsigned h0,h1,h2,h3,l0,l1,l2,l3;
        bf16_split(ox, h0, l0); bf16_split(oy, h1, l1);
        bf16_split(oz, h2, l2); bf16_split(ow, h3, l3);
        const size_t e = ((size_t)(b*SEQ + q0 + row))*DIM + h*DH + tx*4;
        *(uint2*)(AOh + e) = make_uint2(h0 | (h1 << 16), h2 | (h3 << 16));
        *(uint2*)(AOl + e) = make_uint2(l0 | (l1 << 16), l2 | (l3 << 16));
    }
}

// =================== launch ===================
extern "C" void kernel_launch(void* const* d_in, const int* in_sizes, int n_in,
                              void* d_out, int out_size)
{
    const float* xq = (const float*)d_in[0];
    const float* xk = (const float*)d_in[1];
    const float* xv = (const float*)d_in[2];
    const float* Wq = (const float*)d_in[3];
    const float* Wk = (const float*)d_in[4];
    const float* Wv = (const float*)d_in[5];
    const float* Wo = (const float*)d_in[6];
    const float* bo = (const float*)d_in[7];
    float* out = (float*)d_out;

    float *Qp, *Kp, *Vp, *XKp, *XVp;
    cudaGetSymbolAddress((void**)&Qp,  g_Q);
    cudaGetSymbolAddress((void**)&Kp,  g_K);
    cudaGetSymbolAddress((void**)&Vp,  g_V);
    cudaGetSymbolAddress((void**)&XKp, g_XK);
    cudaGetSymbolAddress((void**)&XVp, g_XV);

    __nv_bfloat16 *xqh,*xql,*xkh,*xkl,*xvh,*xvl,*aoh,*aol;
    __nv_bfloat16 *wqh,*wql,*wkh,*wkl,*wvh,*wvl,*woh,*wol;
    cudaGetSymbolAddress((void**)&xqh, g_xqh); cudaGetSymbolAddress((void**)&xql, g_xql);
    cudaGetSymbolAddress((void**)&xkh, g_xkh); cudaGetSymbolAddress((void**)&xkl, g_xkl);
    cudaGetSymbolAddress((void**)&xvh, g_xvh); cudaGetSymbolAddress((void**)&xvl, g_xvl);
    cudaGetSymbolAddress((void**)&aoh, g_AOh); cudaGetSymbolAddress((void**)&aol, g_AOl);
    cudaGetSymbolAddress((void**)&wqh, g_WqTh); cudaGetSymbolAddress((void**)&wql, g_WqTl);
    cudaGetSymbolAddress((void**)&wkh, g_WkTh); cudaGetSymbolAddress((void**)&wkl, g_WkTl);
    cudaGetSymbolAddress((void**)&wvh, g_WvTh); cudaGetSymbolAddress((void**)&wvl, g_WvTl);
    cudaGetSymbolAddress((void**)&woh, g_WoTh); cudaGetSymbolAddress((void**)&wol, g_WoTl);

    const int gemm_smem = 2 * STAGE_B;                          // 122880
    const int attn_smem = (64*PADQ + 64*PADK + 128*PADK) * 4;   // 86016
    cudaFuncSetAttribute(mma_gemm,
                         cudaFuncAttributeMaxDynamicSharedMemorySize, gemm_smem);
    cudaFuncSetAttribute(attn_kernel,
                         cudaFuncAttributeMaxDynamicSharedMemorySize, attn_smem);

    // ---- conversions ----
    const int n4 = MROWS*DIM/4;
    split_hl<<<n4/256, 256>>>((const float4*)xq, (uint2*)xqh, (uint2*)xql, n4);
    split_hl<<<n4/256, 256>>>((const float4*)xk, (uint2*)xkh, (uint2*)xkl, n4);
    split_hl<<<n4/256, 256>>>((const float4*)xv, (uint2*)xvh, (uint2*)xvl, n4);
    dim3 tgrid(DIM/32, DIM/32), tblk(32, 32);
    splitT<<<tgrid, tblk>>>(Wq, wqh, wql);
    splitT<<<tgrid, tblk>>>(Wk, wkh, wkl);
    splitT<<<tgrid, tblk>>>(Wv, wvh, wvl);
    splitT<<<tgrid, tblk>>>(Wo, woh, wol);

    // ---- projection GEMMs (HMMA, 1 wave) ----
    dim3 gg(DIM/256, MROWS/128);   // (2, 64) = 128 CTAs
    mma_gemm<<<gg, 256, gemm_smem>>>(xqh, xql, wqh, wql, nullptr, Qp);
    mma_gemm<<<gg, 256, gemm_smem>>>(xkh, xkl, wkh, wkl, nullptr, Kp);
    mma_gemm<<<gg, 256, gemm_smem>>>(xvh, xvl, wvh, wvl, nullptr, Vp);
    mma_gemm<<<gg, 256, gemm_smem>>>(xqh, xql, wkh, wkl, nullptr, XKp);
    mma_gemm<<<gg, 256, gemm_smem>>>(xqh, xql, wvh, wvl, nullptr, XVp);

    // ---- attention ----
    dim3 ga(SEQ/128, NB*NH);       // (16, 32)
    attn_kernel<<<ga, 256, attn_smem>>>(Qp, Kp, Vp, XKp, XVp, aoh, aol);

    // ---- output GEMM (+bias) ----
    mma_gemm<<<gg, 256, gemm_smem>>>(aoh, aol, woh, wol, bo, out);
}

// round 12
// speedup vs baseline: 2.2911x; 1.5610x over previous
#include <cuda_runtime.h>
#include <cuda_bf16.h>
#include <cstdint>
#include <math.h>

#define NB   4
#define NH   8
#define SEQ  2048
#define DIM  512
#define DH   64
#define MROWS (NB*SEQ)   // 8192

// =================== scratch (static device globals) ===================
__device__ float g_Q [MROWS*DIM];
__device__ float g_K [MROWS*DIM];
__device__ float g_V [MROWS*DIM];
__device__ float g_XK[MROWS*DIM];
__device__ float g_XV[MROWS*DIM];

__device__ __align__(16) __nv_bfloat16 g_xqh[MROWS*DIM], g_xql[MROWS*DIM];
__device__ __align__(16) __nv_bfloat16 g_xkh[MROWS*DIM], g_xkl[MROWS*DIM];
__device__ __align__(16) __nv_bfloat16 g_xvh[MROWS*DIM], g_xvl[MROWS*DIM];
__device__ __align__(16) __nv_bfloat16 g_AOh[MROWS*DIM], g_AOl[MROWS*DIM];

__device__ __align__(16) __nv_bfloat16 g_WqTh[DIM*DIM], g_WqTl[DIM*DIM];
__device__ __align__(16) __nv_bfloat16 g_WkTh[DIM*DIM], g_WkTl[DIM*DIM];
__device__ __align__(16) __nv_bfloat16 g_WvTh[DIM*DIM], g_WvTl[DIM*DIM];
__device__ __align__(16) __nv_bfloat16 g_WoTh[DIM*DIM], g_WoTl[DIM*DIM];

// =================== helpers ===================
__device__ __forceinline__ uint32_t smem_u32(const void* p) {
    uint32_t a;
    asm("{ .reg .u64 t; cvta.to.shared.u64 t, %1; cvt.u32.u64 %0, t; }" : "=r"(a) : "l"(p));
    return a;
}

__device__ __forceinline__ void ldm_x4(uint32_t addr, uint32_t& r0, uint32_t& r1,
                                       uint32_t& r2, uint32_t& r3) {
    asm volatile("ldmatrix.sync.aligned.m8n8.x4.shared.b16 {%0,%1,%2,%3}, [%4];"
                 : "=r"(r0), "=r"(r1), "=r"(r2), "=r"(r3) : "r"(addr));
}
__device__ __forceinline__ void ldm_x4_t(uint32_t addr, uint32_t& r0, uint32_t& r1,
                                         uint32_t& r2, uint32_t& r3) {
    asm volatile("ldmatrix.sync.aligned.m8n8.x4.trans.shared.b16 {%0,%1,%2,%3}, [%4];"
                 : "=r"(r0), "=r"(r1), "=r"(r2), "=r"(r3) : "r"(addr));
}

__device__ __forceinline__ void mma_bf16(float& c0, float& c1, float& c2, float& c3,
                                         uint32_t a0, uint32_t a1, uint32_t a2, uint32_t a3,
                                         uint32_t b0, uint32_t b1) {
    asm volatile(
        "mma.sync.aligned.m16n8k16.row.col.f32.bf16.bf16.f32 "
        "{%0,%1,%2,%3}, {%4,%5,%6,%7}, {%8,%9}, {%0,%1,%2,%3};"
        : "+f"(c0), "+f"(c1), "+f"(c2), "+f"(c3)
        : "r"(a0), "r"(a1), "r"(a2), "r"(a3), "r"(b0), "r"(b1));
}

__device__ __forceinline__ void cp16(uint32_t dst, const void* src) {
    asm volatile("cp.async.cg.shared.global [%0], [%1], 16;" :: "r"(dst), "l"(src));
}
__device__ __forceinline__ void cp_commit() {
    asm volatile("cp.async.commit_group;");
}
template<int N> __device__ __forceinline__ void cp_wait() {
    asm volatile("cp.async.wait_group %0;" :: "n"(N));
}

__device__ __forceinline__ void bf16_split(float x, unsigned& h, unsigned& l) {
    __nv_bfloat16 bh = __float2bfloat16_rn(x);
    float r = x - __bfloat162float(bh);
    __nv_bfloat16 bl = __float2bfloat16_rn(r);
    h = (unsigned)__bfloat16_as_ushort(bh);
    l = (unsigned)__bfloat16_as_ushort(bl);
}
__device__ __forceinline__ float bf_lo(float x) {
    return x - __bfloat162float(__float2bfloat16_rn(x));
}
__device__ __forceinline__ uint32_t pk2(float a, float b) {
    return (uint32_t)__bfloat16_as_ushort(__float2bfloat16_rn(a)) |
           ((uint32_t)__bfloat16_as_ushort(__float2bfloat16_rn(b)) << 16);
}

// =================== conversion kernels ===================
__global__ __launch_bounds__(256) void split_hl(
    const float4* __restrict__ in, uint2* __restrict__ hi, uint2* __restrict__ lo, int n4)
{
    int i = blockIdx.x * 256 + threadIdx.x;
    if (i >= n4) return;
    float4 v = in[i];
    unsigned h0,h1,h2,h3,l0,l1,l2,l3;
    bf16_split(v.x, h0, l0); bf16_split(v.y, h1, l1);
    bf16_split(v.z, h2, l2); bf16_split(v.w, h3, l3);
    hi[i] = make_uint2(h0 | (h1 << 16), h2 | (h3 << 16));
    lo[i] = make_uint2(l0 | (l1 << 16), l2 | (l3 << 16));
}

__global__ __launch_bounds__(1024) void splitT(
    const float* __restrict__ W, __nv_bfloat16* __restrict__ hiT, __nv_bfloat16* __restrict__ loT)
{
    __shared__ float t[32][33];
    const int kb = blockIdx.y * 32, nb = blockIdx.x * 32;
    const int tx = threadIdx.x, ty = threadIdx.y;
    t[ty][tx] = W[(kb + ty) * DIM + nb + tx];
    __syncthreads();
    float x = t[tx][ty];
    unsigned h, l;
    bf16_split(x, h, l);
    hiT[(nb + ty) * DIM + kb + tx] = __ushort_as_bfloat16((unsigned short)h);
    loT[(nb + ty) * DIM + kb + tx] = __ushort_as_bfloat16((unsigned short)l);
}

// =================== HMMA GEMM (round-10, verified) ===================
#define KST   32
#define SSTR  40
#define A_EL  (128*SSTR)
#define B_EL  (256*SSTR)
#define STAGE_EL (2*A_EL + 2*B_EL)
#define STAGE_B  (STAGE_EL*2)

__global__ __launch_bounds__(256) void mma_gemm(
    const __nv_bfloat16* __restrict__ Ah, const __nv_bfloat16* __restrict__ Al,
    const __nv_bfloat16* __restrict__ Bh, const __nv_bfloat16* __restrict__ Bl,
    const float* __restrict__ bias, float* __restrict__ C)
{
    extern __shared__ __align__(16) __nv_bfloat16 sm[];

    const int tid  = threadIdx.x;
    const int wid  = tid >> 5;
    const int lane = tid & 31;
    const int bm = blockIdx.y * 128;
    const int bn = blockIdx.x * 256;
    const int wm = (wid & 1) * 64;
    const int wn = (wid >> 1) * 64;

    const uint32_t sb = smem_u32(sm);

    const int aOff = ((wm + (lane & 15)) * SSTR + (lane >> 4) * 8) * 2;
    const int bn_local = ((lane >> 4) & 1) * 8 + (lane & 7);
    const int bk_local = ((lane >> 3) & 1) * 8;
    const int bOff = ((wn + bn_local) * SSTR + bk_local) * 2;

    const int lrow = tid >> 2;
    const int lsege = (tid & 3) * 8;
    const uint32_t lso = (uint32_t)(lrow * SSTR + lsege) * 2;

    auto prefetch = [&](int j) {
        const int k0 = j * KST;
        const uint32_t st = sb + (j & 1) * STAGE_B;
        #pragma unroll
        for (int it = 0; it < 2; it++) {
            const int row = lrow + it * 64;
            const size_t g = (size_t)(bm + row) * DIM + k0 + lsege;
            const uint32_t d = st + (uint32_t)(it * 64 * SSTR * 2) + lso;
            cp16(d,              Ah + g);
            cp16(d + A_EL * 2,   Al + g);
        }
        #pragma unroll
        for (int it = 0; it < 4; it++) {
            const int row = lrow + it * 64;
            const size_t g = (size_t)(bn + row) * DIM + k0 + lsege;
            const uint32_t d = st + (uint32_t)(2 * A_EL * 2) + (uint32_t)(it * 64 * SSTR * 2) + lso;
            cp16(d,              Bh + g);
            cp16(d + B_EL * 2,   Bl + g);
        }
    };

    float acc[4][8][4];
    #pragma unroll
    for (int i = 0; i < 4; i++)
        #pragma unroll
        for (int j = 0; j < 8; j++)
            #pragma unroll
            for (int r = 0; r < 4; r++) acc[i][j][r] = 0.f;

    prefetch(0);
    cp_commit();

    for (int j = 0; j < DIM / KST; j++) {
        if (j + 1 < DIM / KST) {
            prefetch(j + 1);
            cp_commit();
            cp_wait<1>();
        } else {
            cp_wait<0>();
        }
        __syncthreads();

        const uint32_t st  = sb + (j & 1) * STAGE_B;
        const uint32_t aHi = st + aOff;
        const uint32_t aLo = aHi + A_EL * 2;
        const uint32_t bHi = st + 2 * A_EL * 2 + bOff;
        const uint32_t bLo = bHi + B_EL * 2;

        #pragma unroll
        for (int kk = 0; kk < KST / 16; kk++) {
            const uint32_t kb = kk * 32;
            uint32_t ah[4][4], al[4][4];
            #pragma unroll
            for (int mt = 0; mt < 4; mt++) {
                const uint32_t adr = mt * (16 * SSTR * 2) + kb;
                ldm_x4(aHi + adr, ah[mt][0], ah[mt][1], ah[mt][2], ah[mt][3]);
                ldm_x4(aLo + adr, al[mt][0], al[mt][1], al[mt][2], al[mt][3]);
            }
            #pragma unroll
            for (int h = 0; h < 2; h++) {
                uint32_t bh4[4][2], bl4[4][2];
                #pragma unroll
                for (int p = 0; p < 2; p++) {
                    const uint32_t adr = (h * 2 + p) * (16 * SSTR * 2) + kb;
                    ldm_x4(bHi + adr, bh4[p*2][0], bh4[p*2][1], bh4[p*2+1][0], bh4[p*2+1][1]);
                    ldm_x4(bLo + adr, bl4[p*2][0], bl4[p*2][1], bl4[p*2+1][0], bl4[p*2+1][1]);
                }
                #pragma unroll
                for (int mt = 0; mt < 4; mt++)
                    #pragma unroll
                    for (int q = 0; q < 4; q++) {
                        float* a = acc[mt][h*4 + q];
                        mma_bf16(a[0], a[1], a[2], a[3],
                                 ah[mt][0], ah[mt][1], ah[mt][2], ah[mt][3],
                                 bh4[q][0], bh4[q][1]);
                        mma_bf16(a[0], a[1], a[2], a[3],
                                 ah[mt][0], ah[mt][1], ah[mt][2], ah[mt][3],
                                 bl4[q][0], bl4[q][1]);
                        mma_bf16(a[0], a[1], a[2], a[3],
                                 al[mt][0], al[mt][1], al[mt][2], al[mt][3],
                                 bh4[q][0], bh4[q][1]);
                    }
            }
        }
        __syncthreads();
    }

    const int er = lane >> 2;
    const int ec = (lane & 3) * 2;
    #pragma unroll
    for (int mt = 0; mt < 4; mt++) {
        #pragma unroll
        for (int nt = 0; nt < 8; nt++) {
            const int col = bn + wn + nt * 8 + ec;
            float b0 = 0.f, b1 = 0.f;
            if (bias) { b0 = bias[col]; b1 = bias[col + 1]; }
            const int r0 = bm + wm + mt * 16 + er;
            float2 v0 = make_float2(acc[mt][nt][0] + b0, acc[mt][nt][1] + b1);
            float2 v1 = make_float2(acc[mt][nt][2] + b0, acc[mt][nt][3] + b1);
            *(float2*)(C + (size_t)r0 * DIM + col)       = v0;
            *(float2*)(C + (size_t)(r0 + 8) * DIM + col) = v1;
        }
    }
}

// =================== HMMA flash attention ===================
// CTA: 128 q x one (b,h); 8 warps x 16 q-rows; kv tiles of 64.
// smem union (bf16 elements, stride 72):
//   Q phase : Qh @0 (128x72=9216), Ql @9216
//   KV phase: Kh @0 (64x72=4608), Kl @4608, Vh @9216, Vl @13824
#define ASTR 72

__global__ __launch_bounds__(256, 1) void attn_mma(
    const float* __restrict__ Q,  const float* __restrict__ K,
    const float* __restrict__ V,  const float* __restrict__ XK,
    const float* __restrict__ XV,
    __nv_bfloat16* __restrict__ AOh, __nv_bfloat16* __restrict__ AOl)
{
    __shared__ __align__(16) __nv_bfloat16 sbuf[18432];
    __shared__ float sdiag[128];

    const int tid = threadIdx.x, wid = tid >> 5, lane = tid & 31;
    const int er = lane >> 2, ec = lane & 3;
    const int b  = blockIdx.y >> 3, h = blockIdx.y & 7;
    const int q0 = blockIdx.x * 128;

    const float* Qg = Q  + ((size_t)(b*SEQ + q0))*DIM + h*DH;
    const float* Kg = K  + ((size_t)b*SEQ)*DIM + h*DH;
    const float* Vg = V  + ((size_t)b*SEQ)*DIM + h*DH;

    const uint32_t sb = smem_u32(sbuf);

    // ---- Q tile -> smem bf16 hi/lo, pre-scaled by 1/8 ----
    {
        const int row = tid >> 1, c0 = (tid & 1) * 32;
        const float* src = Qg + (size_t)row*DIM + c0;
        uint2* dh = (uint2*)(sbuf + row*ASTR + c0);
        uint2* dl = (uint2*)(sbuf + 9216 + row*ASTR + c0);
        #pragma unroll
        for (int i = 0; i < 8; i++) {
            float4 v = *(const float4*)(src + i*4);
            unsigned h0,h1,h2,h3,l0,l1,l2,l3;
            bf16_split(v.x*0.125f, h0, l0); bf16_split(v.y*0.125f, h1, l1);
            bf16_split(v.z*0.125f, h2, l2); bf16_split(v.w*0.125f, h3, l3);
            dh[i] = make_uint2(h0 | (h1<<16), h2 | (h3<<16));
            dl[i] = make_uint2(l0 | (l1<<16), l2 | (l3<<16));
        }
    }
    __syncthreads();

    // ---- Q A-fragments (resident across whole kv loop) ----
    uint32_t aqh[4][4], aql[4][4];
    {
        const uint32_t ao = (uint32_t)(((wid*16 + (lane & 15))*ASTR + (lane >> 4)*8) * 2);
        #pragma unroll
        for (int kt = 0; kt < 4; kt++) {
            ldm_x4(sb + ao + kt*32,         aqh[kt][0], aqh[kt][1], aqh[kt][2], aqh[kt][3]);
            ldm_x4(sb + 18432 + ao + kt*32, aql[kt][0], aql[kt][1], aql[kt][2], aql[kt][3]);
        }
    }

    float m0 = -1e30f, m1 = -1e30f, l0s = 0.f, l1s = 0.f;
    float o[8][4];
    #pragma unroll
    for (int i = 0; i < 8; i++)
        #pragma unroll
        for (int j = 0; j < 4; j++) o[i][j] = 0.f;

    // K B-fragment lane offset (non-trans, rows = kv)
    const uint32_t bKoff = (uint32_t)(((((lane>>4)&1)*8 + (lane&7))*ASTR + ((lane>>3)&1)*8) * 2);
    // V B-fragment lane offset (trans, V stored [kv][dh])
    const int vm = lane >> 3;
    const uint32_t vOff = (uint32_t)((((vm&1)*8 + (lane&7))*ASTR + (vm>>1)*8) * 2);

    for (int t = 0; t < SEQ/64; t++) {
        __syncthreads();
        // ---- convert K,V tile -> smem bf16 hi/lo ----
        {
            const int row = tid >> 2, c0 = (tid & 3) * 16;
            const float* ks = Kg + (size_t)(t*64 + row)*DIM + c0;
            const float* vs = Vg + (size_t)(t*64 + row)*DIM + c0;
            uint2* kh = (uint2*)(sbuf + row*ASTR + c0);
            uint2* kl = (uint2*)(sbuf + 4608  + row*ASTR + c0);
            uint2* vh = (uint2*)(sbuf + 9216  + row*ASTR + c0);
            uint2* vl = (uint2*)(sbuf + 13824 + row*ASTR + c0);
            #pragma unroll
            for (int i = 0; i < 4; i++) {
                float4 v = *(const float4*)(ks + i*4);
                unsigned h0,h1,h2,h3,e0,e1,e2,e3;
                bf16_split(v.x, h0, e0); bf16_split(v.y, h1, e1);
                bf16_split(v.z, h2, e2); bf16_split(v.w, h3, e3);
                kh[i] = make_uint2(h0 | (h1<<16), h2 | (h3<<16));
                kl[i] = make_uint2(e0 | (e1<<16), e2 | (e3<<16));
                float4 w = *(const float4*)(vs + i*4);
                bf16_split(w.x, h0, e0); bf16_split(w.y, h1, e1);
                bf16_split(w.z, h2, e2); bf16_split(w.w, h3, e3);
                vh[i] = make_uint2(h0 | (h1<<16), h2 | (h3<<16));
                vl[i] = make_uint2(e0 | (e1<<16), e2 | (e3<<16));
            }
        }
        __syncthreads();

        // ---- S = (Q/8) K^T  (3-pass compensated) ----
        float s[8][4];
        #pragma unroll
        for (int i = 0; i < 8; i++)
            #pragma unroll
            for (int j = 0; j < 4; j++) s[i][j] = 0.f;

        #pragma unroll
        for (int np = 0; np < 4; np++) {
            const uint32_t base = sb + bKoff + np*(16*ASTR*2);
            #pragma unroll
            for (int kt = 0; kt < 4; kt++) {
                uint32_t kh[4], kl[4];
                ldm_x4(base + kt*32,        kh[0], kh[1], kh[2], kh[3]);
                ldm_x4(base + 9216 + kt*32, kl[0], kl[1], kl[2], kl[3]);
                const int nt = np*2;
                mma_bf16(s[nt][0],s[nt][1],s[nt][2],s[nt][3],
                         aqh[kt][0],aqh[kt][1],aqh[kt][2],aqh[kt][3], kh[0],kh[1]);
                mma_bf16(s[nt][0],s[nt][1],s[nt][2],s[nt][3],
                         aqh[kt][0],aqh[kt][1],aqh[kt][2],aqh[kt][3], kl[0],kl[1]);
                mma_bf16(s[nt][0],s[nt][1],s[nt][2],s[nt][3],
                         aql[kt][0],aql[kt][1],aql[kt][2],aql[kt][3], kh[0],kh[1]);
                mma_bf16(s[nt+1][0],s[nt+1][1],s[nt+1][2],s[nt+1][3],
                         aqh[kt][0],aqh[kt][1],aqh[kt][2],aqh[kt][3], kh[2],kh[3]);
                mma_bf16(s[nt+1][0],s[nt+1][1],s[nt+1][2],s[nt+1][3],
                         aqh[kt][0],aqh[kt][1],aqh[kt][2],aqh[kt][3], kl[2],kl[3]);
                mma_bf16(s[nt+1][0],s[nt+1][1],s[nt+1][2],s[nt+1][3],
                         aql[kt][0],aql[kt][1],aql[kt][2],aql[kt][3], kh[2],kh[3]);
            }
        }

        // ---- online softmax (rows er / er+8 per lane) ----
        float rm0 = -1e30f, rm1 = -1e30f;
        #pragma unroll
        for (int nt = 0; nt < 8; nt++) {
            rm0 = fmaxf(rm0, fmaxf(s[nt][0], s[nt][1]));
            rm1 = fmaxf(rm1, fmaxf(s[nt][2], s[nt][3]));
        }
        rm0 = fmaxf(rm0, __shfl_xor_sync(0xffffffffu, rm0, 1));
        rm0 = fmaxf(rm0, __shfl_xor_sync(0xffffffffu, rm0, 2));
        rm1 = fmaxf(rm1, __shfl_xor_sync(0xffffffffu, rm1, 1));
        rm1 = fmaxf(rm1, __shfl_xor_sync(0xffffffffu, rm1, 2));
        const float mn0 = fmaxf(m0, rm0), mn1 = fmaxf(m1, rm1);
        const float c0f = __expf(m0 - mn0), c1f = __expf(m1 - mn1);
        float ps0 = 0.f, ps1 = 0.f;
        #pragma unroll
        for (int nt = 0; nt < 8; nt++) {
            s[nt][0] = __expf(s[nt][0] - mn0); ps0 += s[nt][0];
            s[nt][1] = __expf(s[nt][1] - mn0); ps0 += s[nt][1];
            s[nt][2] = __expf(s[nt][2] - mn1); ps1 += s[nt][2];
            s[nt][3] = __expf(s[nt][3] - mn1); ps1 += s[nt][3];
        }
        ps0 += __shfl_xor_sync(0xffffffffu, ps0, 1);
        ps0 += __shfl_xor_sync(0xffffffffu, ps0, 2);
        ps1 += __shfl_xor_sync(0xffffffffu, ps1, 1);
        ps1 += __shfl_xor_sync(0xffffffffu, ps1, 2);
        l0s = l0s*c0f + ps0; l1s = l1s*c1f + ps1;
        m0 = mn0; m1 = mn1;
        #pragma unroll
        for (int nt = 0; nt < 8; nt++) {
            o[nt][0] *= c0f; o[nt][1] *= c0f;
            o[nt][2] *= c1f; o[nt][3] *= c1f;
        }

        // ---- P -> A fragments (FA2 register trick), hi/lo ----
        uint32_t ph[4][4], pl[4][4];
        #pragma unroll
        for (int kt = 0; kt < 4; kt++) {
            const int nt = 2*kt, np1 = 2*kt + 1;
            ph[kt][0] = pk2(s[nt][0],  s[nt][1]);
            ph[kt][1] = pk2(s[nt][2],  s[nt][3]);
            ph[kt][2] = pk2(s[np1][0], s[np1][1]);
            ph[kt][3] = pk2(s[np1][2], s[np1][3]);
            pl[kt][0] = pk2(bf_lo(s[nt][0]),  bf_lo(s[nt][1]));
            pl[kt][1] = pk2(bf_lo(s[nt][2]),  bf_lo(s[nt][3]));
            pl[kt][2] = pk2(bf_lo(s[np1][0]), bf_lo(s[np1][1]));
            pl[kt][3] = pk2(bf_lo(s[np1][2]), bf_lo(s[np1][3]));
        }

        // ---- O += P V  (ldmatrix.trans on V[kv][dh], 3-pass) ----
        #pragma unroll
        for (int np = 0; np < 4; np++) {
            #pragma unroll
            for (int kt = 0; kt < 4; kt++) {
                uint32_t vh[4], vl[4];
                const uint32_t va = sb + 18432 + vOff + kt*(16*ASTR*2) + np*32;
                ldm_x4_t(va,        vh[0], vh[1], vh[2], vh[3]);
                ldm_x4_t(va + 9216, vl[0], vl[1], vl[2], vl[3]);
                const int nt = np*2;
                mma_bf16(o[nt][0],o[nt][1],o[nt][2],o[nt][3],
                         ph[kt][0],ph[kt][1],ph[kt][2],ph[kt][3], vh[0],vh[1]);
                mma_bf16(o[nt][0],o[nt][1],o[nt][2],o[nt][3],
                         ph[kt][0],ph[kt][1],ph[kt][2],ph[kt][3], vl[0],vl[1]);
                mma_bf16(o[nt][0],o[nt][1],o[nt][2],o[nt][3],
                         pl[kt][0],pl[kt][1],pl[kt][2],pl[kt][3], vh[0],vh[1]);
                mma_bf16(o[nt+1][0],o[nt+1][1],o[nt+1][2],o[nt+1][3],
                         ph[kt][0],ph[kt][1],ph[kt][2],ph[kt][3], vh[2],vh[3]);
                mma_bf16(o[nt+1][0],o[nt+1][1],o[nt+1][2],o[nt+1][3],
                         ph[kt][0],ph[kt][1],ph[kt][2],ph[kt][3], vl[2],vl[3]);
                mma_bf16(o[nt+1][0],o[nt+1][1],o[nt+1][2],o[nt+1][3],
                         pl[kt][0],pl[kt][1],pl[kt][2],pl[kt][3], vh[2],vh[3]);
            }
        }
    }

    // ---- diagonal logit: dl = scale * dot(q_row, xk_row) ----
    {
        const int rl = lane >> 1, half = lane & 1;
        const size_t g = (size_t)(b*SEQ + q0 + wid*16 + rl)*DIM + h*DH + half*32;
        const float* qd = Q  + g;
        const float* xd = XK + g;
        float dl = 0.f;
        #pragma unroll
        for (int i = 0; i < 8; i++) {
            float4 a = *(const float4*)(qd + i*4);
            float4 c = *(const float4*)(xd + i*4);
            dl = fmaf(a.x, c.x, fmaf(a.y, c.y, fmaf(a.z, c.z, fmaf(a.w, c.w, dl))));
        }
        dl += __shfl_xor_sync(0xffffffffu, dl, 1);
        if (half == 0) sdiag[wid*16 + rl] = dl * 0.125f;
    }
    __syncwarp();
    const float dl0 = sdiag[wid*16 + er];
    const float dl1 = sdiag[wid*16 + er + 8];

    // ---- merge diag + finalize + store bf16 hi/lo ----
    {
        const float mn0 = fmaxf(m0, dl0), mn1 = fmaxf(m1, dl1);
        const float c0f = __expf(m0 - mn0), c1f = __expf(m1 - mn1);
        const float pd0 = __expf(dl0 - mn0), pd1 = __expf(dl1 - mn1);
        const float inv0 = 1.0f / (l0s*c0f + pd0);
        const float inv1 = 1.0f / (l1s*c1f + pd1);
        const size_t gr0 = (size_t)(b*SEQ + q0 + wid*16 + er);
        const size_t gr1 = gr0 + 8;
        #pragma unroll
        for (int nt = 0; nt < 8; nt++) {
            const int col = h*DH + nt*8 + ec*2;
            float2 xv0 = *(const float2*)(XV + gr0*DIM + col);
            float2 xv1 = *(const float2*)(XV + gr1*DIM + col);
            float ox0 = (o[nt][0]*c0f + pd0*xv0.x) * inv0;
            float oy0 = (o[nt][1]*c0f + pd0*xv0.y) * inv0;
            float ox1 = (o[nt][2]*c1f + pd1*xv1.x) * inv1;
            float oy1 = (o[nt][3]*c1f + pd1*xv1.y) * inv1;
            unsigned ha,hb,la,lb;
            bf16_split(ox0, ha, la); bf16_split(oy0, hb, lb);
            *(uint32_t*)(AOh + gr0*DIM + col) = ha | (hb<<16);
            *(uint32_t*)(AOl + gr0*DIM + col) = la | (lb<<16);
            bf16_split(ox1, ha, la); bf16_split(oy1, hb, lb);
            *(uint32_t*)(AOh + gr1*DIM + col) = ha | (hb<<16);
            *(uint32_t*)(AOl + gr1*DIM + col) = la | (lb<<16);
        }
    }
}

// =================== launch ===================
extern "C" void kernel_launch(void* const* d_in, const int* in_sizes, int n_in,
                              void* d_out, int out_size)
{
    const float* xq = (const float*)d_in[0];
    const float* xk = (const float*)d_in[1];
    const float* xv = (const float*)d_in[2];
    const float* Wq = (const float*)d_in[3];
    const float* Wk = (const float*)d_in[4];
    const float* Wv = (const float*)d_in[5];
    const float* Wo = (const float*)d_in[6];
    const float* bo = (const float*)d_in[7];
    float* out = (float*)d_out;

    float *Qp, *Kp, *Vp, *XKp, *XVp;
    cudaGetSymbolAddress((void**)&Qp,  g_Q);
    cudaGetSymbolAddress((void**)&Kp,  g_K);
    cudaGetSymbolAddress((void**)&Vp,  g_V);
    cudaGetSymbolAddress((void**)&XKp, g_XK);
    cudaGetSymbolAddress((void**)&XVp, g_XV);

    __nv_bfloat16 *xqh,*xql,*xkh,*xkl,*xvh,*xvl,*aoh,*aol;
    __nv_bfloat16 *wqh,*wql,*wkh,*wkl,*wvh,*wvl,*woh,*wol;
    cudaGetSymbolAddress((void**)&xqh, g_xqh); cudaGetSymbolAddress((void**)&xql, g_xql);
    cudaGetSymbolAddress((void**)&xkh, g_xkh); cudaGetSymbolAddress((void**)&xkl, g_xkl);
    cudaGetSymbolAddress((void**)&xvh, g_xvh); cudaGetSymbolAddress((void**)&xvl, g_xvl);
    cudaGetSymbolAddress((void**)&aoh, g_AOh); cudaGetSymbolAddress((void**)&aol, g_AOl);
    cudaGetSymbolAddress((void**)&wqh, g_WqTh); cudaGetSymbolAddress((void**)&wql, g_WqTl);
    cudaGetSymbolAddress((void**)&wkh, g_WkTh); cudaGetSymbolAddress((void**)&wkl, g_WkTl);
    cudaGetSymbolAddress((void**)&wvh, g_WvTh); cudaGetSymbolAddress((void**)&wvl, g_WvTl);
    cudaGetSymbolAddress((void**)&woh, g_WoTh); cudaGetSymbolAddress((void**)&wol, g_WoTl);

    const int gemm_smem = 2 * STAGE_B;
    cudaFuncSetAttribute(mma_gemm,
                         cudaFuncAttributeMaxDynamicSharedMemorySize, gemm_smem);

    // ---- conversions ----
    const int n4 = MROWS*DIM/4;
    split_hl<<<n4/256, 256>>>((const float4*)xq, (uint2*)xqh, (uint2*)xql, n4);
    split_hl<<<n4/256, 256>>>((const float4*)xk, (uint2*)xkh, (uint2*)xkl, n4);
    split_hl<<<n4/256, 256>>>((const float4*)xv, (uint2*)xvh, (uint2*)xvl, n4);
    dim3 tgrid(DIM/32, DIM/32), tblk(32, 32);
    splitT<<<tgrid, tblk>>>(Wq, wqh, wql);
    splitT<<<tgrid, tblk>>>(Wk, wkh, wkl);
    splitT<<<tgrid, tblk>>>(Wv, wvh, wvl);
    splitT<<<tgrid, tblk>>>(Wo, woh, wol);

    // ---- projection GEMMs ----
    dim3 gg(DIM/256, MROWS/128);
    mma_gemm<<<gg, 256, gemm_smem>>>(xqh, xql, wqh, wql, nullptr, Qp);
    mma_gemm<<<gg, 256, gemm_smem>>>(xkh, xkl, wkh, wkl, nullptr, Kp);
    mma_gemm<<<gg, 256, gemm_smem>>>(xvh, xvl, wvh, wvl, nullptr, Vp);
    mma_gemm<<<gg, 256, gemm_smem>>>(xqh, xql, wkh, wkl, nullptr, XKp);
    mma_gemm<<<gg, 256, gemm_smem>>>(xqh, xql, wvh, wvl, nullptr, XVp);

    // ---- HMMA attention ----
    dim3 ga(SEQ/128, NB*NH);       // (16, 32)
    attn_mma<<<ga, 256>>>(Qp, Kp, Vp, XKp, XVp, aoh, aol);

    // ---- output GEMM (+bias) ----
    mma_gemm<<<gg, 256, gemm_smem>>>(aoh, aol, woh, wol, bo, out);
}